// round 1
// baseline (speedup 1.0000x reference)
#include <cuda_runtime.h>
#include <cuda_bf16.h>
#include <cstdint>

// Problem shapes (fixed by setup_inputs)
#define M_DIM 4096
#define K_DIM 2048
#define N_DIM 4096

// ---------------- device scratch (no allocation allowed) ----------------
__device__ __nv_bfloat16 g_qA[(size_t)M_DIM * K_DIM];   // centered quantized A (bf16)
__device__ __nv_bfloat16 g_qB[(size_t)K_DIM * N_DIM];   // centered quantized B (bf16)

#define MMG 1024
__device__ float g_pminA[MMG], g_pmaxA[MMG], g_pminB[MMG], g_pmaxB[MMG];
__device__ float g_scaleA, g_zeroA, g_scaleB, g_zeroB, g_sAB;

// ---------------- helpers ----------------
__device__ __forceinline__ uint32_t smem_u32(const void* p) {
    return (uint32_t)__cvta_generic_to_shared(p);
}
__device__ __forceinline__ void cp_async16(uint32_t dst, const void* src) {
    asm volatile("cp.async.cg.shared.global [%0], [%1], 16;\n" :: "r"(dst), "l"(src) : "memory");
}
__device__ __forceinline__ void cp_commit() {
    asm volatile("cp.async.commit_group;\n" ::: "memory");
}
template <int N>
__device__ __forceinline__ void cp_wait() {
    asm volatile("cp.async.wait_group %0;\n" :: "n"(N) : "memory");
}
__device__ __forceinline__ void ldsm_x4(uint32_t* r, uint32_t addr) {
    asm volatile("ldmatrix.sync.aligned.m8n8.x4.shared.b16 {%0,%1,%2,%3}, [%4];\n"
                 : "=r"(r[0]), "=r"(r[1]), "=r"(r[2]), "=r"(r[3]) : "r"(addr));
}
__device__ __forceinline__ void ldsm_x4_t(uint32_t* r, uint32_t addr) {
    asm volatile("ldmatrix.sync.aligned.m8n8.x4.trans.shared.b16 {%0,%1,%2,%3}, [%4];\n"
                 : "=r"(r[0]), "=r"(r[1]), "=r"(r[2]), "=r"(r[3]) : "r"(addr));
}
__device__ __forceinline__ void mma_bf16(float* d, const uint32_t* a, const uint32_t* b) {
    asm volatile("mma.sync.aligned.m16n8k16.row.col.f32.bf16.bf16.f32 "
                 "{%0,%1,%2,%3}, {%4,%5,%6,%7}, {%8,%9}, {%0,%1,%2,%3};\n"
                 : "+f"(d[0]), "+f"(d[1]), "+f"(d[2]), "+f"(d[3])
                 : "r"(a[0]), "r"(a[1]), "r"(a[2]), "r"(a[3]),
                   "r"(b[0]), "r"(b[1]));
}

// ---------------- 1) per-tensor min/max partials ----------------
__global__ void minmax_partial(const float* __restrict__ x, int n, int which) {
    float vmin = 3.4028235e38f, vmax = -3.4028235e38f;
    int idx = blockIdx.x * blockDim.x + threadIdx.x;
    int stride = gridDim.x * blockDim.x;
    int n4 = n >> 2;
    const float4* x4 = (const float4*)x;
    for (int i = idx; i < n4; i += stride) {
        float4 v = x4[i];
        vmin = fminf(vmin, fminf(fminf(v.x, v.y), fminf(v.z, v.w)));
        vmax = fmaxf(vmax, fmaxf(fmaxf(v.x, v.y), fmaxf(v.z, v.w)));
    }
    // tail (n is a multiple of 4 for our shapes; keep for safety)
    for (int i = (n4 << 2) + idx; i < n; i += stride) {
        float v = x[i];
        vmin = fminf(vmin, v); vmax = fmaxf(vmax, v);
    }
    #pragma unroll
    for (int o = 16; o > 0; o >>= 1) {
        vmin = fminf(vmin, __shfl_xor_sync(0xffffffffu, vmin, o));
        vmax = fmaxf(vmax, __shfl_xor_sync(0xffffffffu, vmax, o));
    }
    __shared__ float smin[8], smax[8];
    int warp = threadIdx.x >> 5, lane = threadIdx.x & 31;
    if (lane == 0) { smin[warp] = vmin; smax[warp] = vmax; }
    __syncthreads();
    if (threadIdx.x == 0) {
        float m0 = smin[0], m1 = smax[0];
        #pragma unroll
        for (int w = 1; w < 8; w++) { m0 = fminf(m0, smin[w]); m1 = fmaxf(m1, smax[w]); }
        if (which) { g_pminB[blockIdx.x] = m0; g_pmaxB[blockIdx.x] = m1; }
        else       { g_pminA[blockIdx.x] = m0; g_pmaxA[blockIdx.x] = m1; }
    }
}

// ---------------- 2) finalize scales/zeros ----------------
__global__ void finalize_scales() {
    __shared__ float s0[256], s1[256], s2[256], s3[256];
    int t = threadIdx.x;
    float mnA = 3.4028235e38f, mxA = -3.4028235e38f;
    float mnB = 3.4028235e38f, mxB = -3.4028235e38f;
    for (int i = t; i < MMG; i += 256) {
        mnA = fminf(mnA, g_pminA[i]); mxA = fmaxf(mxA, g_pmaxA[i]);
        mnB = fminf(mnB, g_pminB[i]); mxB = fmaxf(mxB, g_pmaxB[i]);
    }
    s0[t] = mnA; s1[t] = mxA; s2[t] = mnB; s3[t] = mxB;
    __syncthreads();
    for (int o = 128; o > 0; o >>= 1) {
        if (t < o) {
            s0[t] = fminf(s0[t], s0[t + o]);
            s1[t] = fmaxf(s1[t], s1[t + o]);
            s2[t] = fminf(s2[t], s2[t + o]);
            s3[t] = fmaxf(s3[t], s3[t + o]);
        }
        __syncthreads();
    }
    if (t == 0) {
        float sA = __fdiv_rn(s1[0] - s0[0], 255.0f);
        float zA = rintf(__fdiv_rn(-s0[0], sA));
        float sB = __fdiv_rn(s3[0] - s2[0], 255.0f);
        float zB = rintf(__fdiv_rn(-s2[0], sB));
        g_scaleA = sA; g_zeroA = zA;
        g_scaleB = sB; g_zeroB = zB;
        g_sAB = sA * sB;
    }
}

// ---------------- 3) quantize + center into bf16 ----------------
__global__ void quantize_kernel(const float* __restrict__ x, int n4, int which) {
    int i = blockIdx.x * blockDim.x + threadIdx.x;
    if (i >= n4) return;
    float s = which ? g_scaleB : g_scaleA;
    float z = which ? g_zeroB  : g_zeroA;
    __nv_bfloat16* q = which ? g_qB : g_qA;
    float4 v = ((const float4*)x)[i];
    float q0 = fminf(fmaxf(rintf(__fdiv_rn(v.x, s)) + z, 0.0f), 255.0f) - z;
    float q1 = fminf(fmaxf(rintf(__fdiv_rn(v.y, s)) + z, 0.0f), 255.0f) - z;
    float q2 = fminf(fmaxf(rintf(__fdiv_rn(v.z, s)) + z, 0.0f), 255.0f) - z;
    float q3 = fminf(fmaxf(rintf(__fdiv_rn(v.w, s)) + z, 0.0f), 255.0f) - z;
    __nv_bfloat16 b0 = __float2bfloat16_rn(q0);
    __nv_bfloat16 b1 = __float2bfloat16_rn(q1);
    __nv_bfloat16 b2 = __float2bfloat16_rn(q2);
    __nv_bfloat16 b3 = __float2bfloat16_rn(q3);
    unsigned short h0, h1, h2, h3;
    memcpy(&h0, &b0, 2); memcpy(&h1, &b1, 2); memcpy(&h2, &b2, 2); memcpy(&h3, &b3, 2);
    uint32_t u0 = (uint32_t)h0 | ((uint32_t)h1 << 16);
    uint32_t u1 = (uint32_t)h2 | ((uint32_t)h3 << 16);
    ((uint2*)q)[i] = make_uint2(u0, u1);
}

// ---------------- 4) bf16 GEMM (mma.sync m16n8k16, double-buffered cp.async) ----------------
#define BM 128
#define BN 128
#define BK 32
#define LDA_S 40    // halfs per A smem row (32 + 8 pad; 80B row stride, 16B aligned)
#define LDB_S 136   // halfs per B smem row (128 + 8 pad; 272B row stride, 16B aligned)

__global__ __launch_bounds__(256, 1) void gemm_bf16(float* __restrict__ C) {
    __shared__ __nv_bfloat16 As[2][BM * LDA_S];
    __shared__ __nv_bfloat16 Bs[2][BK * LDB_S];

    const int tid = threadIdx.x;
    const int warpId = tid >> 5, lane = tid & 31;
    const int warpM = warpId & 3;   // 4 warps along M
    const int warpN = warpId >> 2;  // 2 warps along N
    const int bm = blockIdx.y * BM;
    const int bn = blockIdx.x * BN;

    const __nv_bfloat16* __restrict__ Aq = g_qA;
    const __nv_bfloat16* __restrict__ Bq = g_qB;

    float acc[2][8][4];
    #pragma unroll
    for (int mt = 0; mt < 2; mt++)
        #pragma unroll
        for (int nt = 0; nt < 8; nt++)
            #pragma unroll
            for (int r = 0; r < 4; r++)
                acc[mt][nt][r] = 0.0f;

    auto load_stage = [&](int kt, int buf) {
        const int k0 = kt * BK;
        // A tile: 128 rows x 32 halfs = 512 x 16B chunks (4 chunks/row)
        #pragma unroll
        for (int c = tid; c < 512; c += 256) {
            int row = c >> 2, cc = c & 3;
            const __nv_bfloat16* src = Aq + (size_t)(bm + row) * K_DIM + k0 + cc * 8;
            cp_async16(smem_u32(&As[buf][row * LDA_S + cc * 8]), src);
        }
        // B tile: 32 rows x 128 halfs = 512 x 16B chunks (16 chunks/row)
        #pragma unroll
        for (int c = tid; c < 512; c += 256) {
            int row = c >> 4, cc = c & 15;
            const __nv_bfloat16* src = Bq + (size_t)(k0 + row) * N_DIM + bn + cc * 8;
            cp_async16(smem_u32(&Bs[buf][row * LDB_S + cc * 8]), src);
        }
        cp_commit();
    };

    const int KT = K_DIM / BK;  // 64
    load_stage(0, 0);

    for (int kt = 0; kt < KT; kt++) {
        const int buf = kt & 1;
        if (kt + 1 < KT) {
            load_stage(kt + 1, (kt + 1) & 1);
            cp_wait<1>();
        } else {
            cp_wait<0>();
        }
        __syncthreads();

        #pragma unroll
        for (int ks = 0; ks < 2; ks++) {
            uint32_t a[2][4];
            #pragma unroll
            for (int mt = 0; mt < 2; mt++) {
                const __nv_bfloat16* p =
                    &As[buf][(warpM * 32 + mt * 16 + (lane & 15)) * LDA_S + ks * 16 + (lane >> 4) * 8];
                ldsm_x4(a[mt], smem_u32(p));
            }
            uint32_t b[8][2];
            #pragma unroll
            for (int np = 0; np < 4; np++) {
                const __nv_bfloat16* p =
                    &Bs[buf][(ks * 16 + (lane & 15)) * LDB_S + warpN * 64 + np * 16 + (lane >> 4) * 8];
                uint32_t r[4];
                ldsm_x4_t(r, smem_u32(p));
                b[2 * np][0] = r[0]; b[2 * np][1] = r[1];
                b[2 * np + 1][0] = r[2]; b[2 * np + 1][1] = r[3];
            }
            #pragma unroll
            for (int mt = 0; mt < 2; mt++)
                #pragma unroll
                for (int nt = 0; nt < 8; nt++)
                    mma_bf16(acc[mt][nt], a[mt], b[nt]);
        }
        __syncthreads();
    }

    // epilogue: multiply by sA*sB, write fp32 C
    const float s = g_sAB;
    const int groupID = lane >> 2, tig = lane & 3;
    #pragma unroll
    for (int mt = 0; mt < 2; mt++) {
        #pragma unroll
        for (int nt = 0; nt < 8; nt++) {
            int row0 = bm + warpM * 32 + mt * 16 + groupID;
            int col  = bn + warpN * 64 + nt * 8 + tig * 2;
            float2 v0 = make_float2(acc[mt][nt][0] * s, acc[mt][nt][1] * s);
            float2 v1 = make_float2(acc[mt][nt][2] * s, acc[mt][nt][3] * s);
            *(float2*)&C[(size_t)row0 * N_DIM + col]       = v0;
            *(float2*)&C[(size_t)(row0 + 8) * N_DIM + col] = v1;
        }
    }
}

// ---------------- launch ----------------
extern "C" void kernel_launch(void* const* d_in, const int* in_sizes, int n_in,
                              void* d_out, int out_size) {
    const float* A = (const float*)d_in[0];  // [4096, 2048]
    const float* B = (const float*)d_in[1];  // [2048, 4096]
    float* C = (float*)d_out;                // [4096, 4096]

    const int nA = M_DIM * K_DIM;
    const int nB = K_DIM * N_DIM;

    minmax_partial<<<MMG, 256>>>(A, nA, 0);
    minmax_partial<<<MMG, 256>>>(B, nB, 1);
    finalize_scales<<<1, 256>>>();

    quantize_kernel<<<(nA / 4 + 255) / 256, 256>>>(A, nA / 4, 0);
    quantize_kernel<<<(nB / 4 + 255) / 256, 256>>>(B, nB / 4, 1);

    dim3 grid(N_DIM / BN, M_DIM / BM);  // 32 x 32
    gemm_bf16<<<grid, 256>>>(C);
}

// round 8
// speedup vs baseline: 2.7827x; 2.7827x over previous
#include <cuda_runtime.h>
#include <cuda_bf16.h>
#include <cstdint>

// Problem shapes (fixed by setup_inputs)
#define M_DIM 4096
#define K_DIM 2048
#define N_DIM 4096

// Detect tcgen05 availability per compilation pass (compute_103a yes, compute_103 no)
#define HAS_TCGEN05 0
#ifdef __CUDA_ARCH__
#ifdef __CUDA_ARCH_HAS_FEATURE__
#if __CUDA_ARCH_HAS_FEATURE__(SM103_ALL) || __CUDA_ARCH_HAS_FEATURE__(SM100_ALL)
#undef HAS_TCGEN05
#define HAS_TCGEN05 1
#endif
#endif
#endif

// ---------------- device scratch (no allocation allowed) ----------------
__device__ __nv_bfloat16 g_qA[(size_t)M_DIM * K_DIM];   // centered quantized A (bf16), [M,K] K-major
__device__ __nv_bfloat16 g_qB[(size_t)N_DIM * K_DIM];   // centered quantized B^T (bf16), [N,K] K-major

#define MMG 1024
__device__ float g_pminA[MMG], g_pmaxA[MMG], g_pminB[MMG], g_pmaxB[MMG];
__device__ float g_scaleA, g_zeroA, g_scaleB, g_zeroB, g_sAB;

// ---------------- generic helpers (valid on all targets) ----------------
__device__ __forceinline__ uint32_t smem_u32(const void* p) {
    return (uint32_t)__cvta_generic_to_shared(p);
}
__device__ __forceinline__ void cp_async16(uint32_t dst, const void* src) {
    asm volatile("cp.async.cg.shared.global [%0], [%1], 16;\n" :: "r"(dst), "l"(src) : "memory");
}
__device__ __forceinline__ void cp_commit() {
    asm volatile("cp.async.commit_group;\n" ::: "memory");
}
template <int N>
__device__ __forceinline__ void cp_wait() {
    asm volatile("cp.async.wait_group %0;\n" :: "n"(N) : "memory");
}
__device__ __forceinline__ void ldsm_x4(uint32_t* r, uint32_t addr) {
    asm volatile("ldmatrix.sync.aligned.m8n8.x4.shared.b16 {%0,%1,%2,%3}, [%4];\n"
                 : "=r"(r[0]), "=r"(r[1]), "=r"(r[2]), "=r"(r[3]) : "r"(addr));
}
__device__ __forceinline__ void mma_bf16(float* d, const uint32_t* a, const uint32_t* b) {
    asm volatile("mma.sync.aligned.m16n8k16.row.col.f32.bf16.bf16.f32 "
                 "{%0,%1,%2,%3}, {%4,%5,%6,%7}, {%8,%9}, {%0,%1,%2,%3};\n"
                 : "+f"(d[0]), "+f"(d[1]), "+f"(d[2]), "+f"(d[3])
                 : "r"(a[0]), "r"(a[1]), "r"(a[2]), "r"(a[3]),
                   "r"(b[0]), "r"(b[1]));
}

#define SMEM_SWIZZLE_128B(byte_offset) ((byte_offset) ^ (((byte_offset) >> 3) & 0x70))

// ---------------- tcgen05-only helpers ----------------
#if HAS_TCGEN05
__device__ __forceinline__ uint32_t elect_one_pred() {
    uint32_t pred;
    asm volatile("{\n\t.reg .pred p;\n\telect.sync _|p, 0xFFFFFFFF;\n\tselp.b32 %0, 1, 0, p;\n\t}"
                 : "=r"(pred));
    return pred;
}

// SW128 K-major SMEM descriptor (Blackwell): layout=SW128, version=1, SBO=64, LBO=1
static constexpr uint64_t SMEM_DESC_BASE_SW128 =
    (uint64_t(2) << 61) | (uint64_t(1) << 46) | (uint64_t(64) << 32) | (uint64_t(1) << 16);
#define MAKE_SMEM_DESC(base_addr) \
    (SMEM_DESC_BASE_SW128 | ((uint64_t)((base_addr) >> 4) & 0x3FFF))

#define MBARRIER_INIT(mbar, count) \
    asm volatile("mbarrier.init.shared.b64 [%0], %1;" :: "r"((uint32_t)(mbar)), "r"((uint32_t)(count)) : "memory")
#define MBARRIER_INVAL(mbar) \
    asm volatile("mbarrier.inval.shared.b64 [%0];" :: "r"((uint32_t)(mbar)) : "memory")
#define MBARRIER_ARRIVE(mbar) \
    asm volatile("mbarrier.arrive.shared.b64 _, [%0];" :: "r"((uint32_t)(mbar)) : "memory")
#define MBARRIER_WAIT_PARITY(mbar, parity) do { \
    uint32_t _mbar = (uint32_t)(mbar); \
    uint32_t _par = (uint32_t)(parity); \
    uint32_t _done; \
    asm volatile("{\n\t.reg .pred p;\n\t" \
        "mbarrier.try_wait.parity.acquire.cta.shared::cta.b64 p, [%1], %2;\n\t" \
        "selp.b32 %0, 1, 0, p;\n\t}" : "=r"(_done) : "r"(_mbar), "r"(_par) : "memory"); \
    if (!_done) { \
        asm volatile("{\n\t.reg .pred P1;\n\t" \
            "WAIT_LOOP_%=:\n\t" \
            "mbarrier.try_wait.parity.acquire.cta.shared::cta.b64 P1, [%0], %1, 0x989680;\n\t" \
            "@P1 bra.uni WAIT_DONE_%=;\n\t" \
            "bra.uni WAIT_LOOP_%=;\n\t" \
            "WAIT_DONE_%=:\n\t}" :: "r"(_mbar), "r"(_par) : "memory"); \
    } \
} while (0)

#define FENCE_PROXY_ASYNC() \
    asm volatile("fence.proxy.async.shared::cta;" ::: "memory")
#define TCGEN05_FENCE_AFTER() \
    asm volatile("tcgen05.fence::after_thread_sync;" ::: "memory")
#define TCGEN05_FENCE_BEFORE() \
    asm volatile("tcgen05.fence::before_thread_sync;" ::: "memory")
#define TCGEN05_ALLOC(smem_addr, nCols) \
    asm volatile("tcgen05.alloc.cta_group::1.sync.aligned.shared::cta.b32 [%0], %1;" \
                 :: "r"((uint32_t)(smem_addr)), "r"((uint32_t)(nCols)) : "memory")
#define TCGEN05_DEALLOC(tmem, nCols) \
    asm volatile("tcgen05.dealloc.cta_group::1.sync.aligned.b32 %0, %1;" :: "r"(tmem), "r"((uint32_t)(nCols)))
#define TCGEN05_RELINQUISH() \
    asm volatile("tcgen05.relinquish_alloc_permit.cta_group::1.sync.aligned;")
#define TCGEN05_COMMIT(mbar) \
    asm volatile("tcgen05.commit.cta_group::1.mbarrier::arrive::one.shared::cluster.b64 [%0];" \
                 :: "r"((uint32_t)(mbar)) : "memory")
#define TCGEN05_WAIT_LD() \
    asm volatile("tcgen05.wait::ld.sync.aligned;" ::: "memory")

#define TCGEN05_LD_32X32B_X32(r, tmem_addr) \
    asm volatile("tcgen05.ld.sync.aligned.32x32b.x32.b32 " \
        "{%0, %1, %2, %3, %4, %5, %6, %7, %8, %9, %10, %11, %12, %13, %14, %15, " \
        "%16, %17, %18, %19, %20, %21, %22, %23, %24, %25, %26, %27, %28, %29, %30, %31}, [%32];" \
        : "=r"((r)[0]), "=r"((r)[1]), "=r"((r)[2]), "=r"((r)[3]), \
          "=r"((r)[4]), "=r"((r)[5]), "=r"((r)[6]), "=r"((r)[7]), \
          "=r"((r)[8]), "=r"((r)[9]), "=r"((r)[10]), "=r"((r)[11]), \
          "=r"((r)[12]), "=r"((r)[13]), "=r"((r)[14]), "=r"((r)[15]), \
          "=r"((r)[16]), "=r"((r)[17]), "=r"((r)[18]), "=r"((r)[19]), \
          "=r"((r)[20]), "=r"((r)[21]), "=r"((r)[22]), "=r"((r)[23]), \
          "=r"((r)[24]), "=r"((r)[25]), "=r"((r)[26]), "=r"((r)[27]), \
          "=r"((r)[28]), "=r"((r)[29]), "=r"((r)[30]), "=r"((r)[31]) \
        : "r"(tmem_addr))

__device__ __forceinline__ void mma_f16_ss(uint32_t d_tmem, uint64_t a_desc, uint64_t b_desc,
                                           uint32_t idesc, uint32_t enable_d) {
    asm volatile(
        "{\n\t.reg .pred p;\n\t"
        "setp.ne.u32 p, %4, 0;\n\t"
        "tcgen05.mma.cta_group::1.kind::f16 [%0], %1, %2, %3, {%5, %5, %5, %5}, p;\n\t}"
        :: "r"(d_tmem), "l"(a_desc), "l"(b_desc), "r"(idesc), "r"(enable_d), "r"(0u)
        : "memory");
}
#endif  // HAS_TCGEN05

// ---------------- 1) per-tensor min/max partials ----------------
__global__ void minmax_partial(const float* __restrict__ x, int n, int which) {
    float vmin = 3.4028235e38f, vmax = -3.4028235e38f;
    int idx = blockIdx.x * blockDim.x + threadIdx.x;
    int stride = gridDim.x * blockDim.x;
    int n4 = n >> 2;
    const float4* x4 = (const float4*)x;
    for (int i = idx; i < n4; i += stride) {
        float4 v = x4[i];
        vmin = fminf(vmin, fminf(fminf(v.x, v.y), fminf(v.z, v.w)));
        vmax = fmaxf(vmax, fmaxf(fmaxf(v.x, v.y), fmaxf(v.z, v.w)));
    }
    #pragma unroll
    for (int o = 16; o > 0; o >>= 1) {
        vmin = fminf(vmin, __shfl_xor_sync(0xffffffffu, vmin, o));
        vmax = fmaxf(vmax, __shfl_xor_sync(0xffffffffu, vmax, o));
    }
    __shared__ float smin[8], smax[8];
    int warp = threadIdx.x >> 5, lane = threadIdx.x & 31;
    if (lane == 0) { smin[warp] = vmin; smax[warp] = vmax; }
    __syncthreads();
    if (threadIdx.x == 0) {
        float m0 = smin[0], m1 = smax[0];
        #pragma unroll
        for (int w = 1; w < 8; w++) { m0 = fminf(m0, smin[w]); m1 = fmaxf(m1, smax[w]); }
        if (which) { g_pminB[blockIdx.x] = m0; g_pmaxB[blockIdx.x] = m1; }
        else       { g_pminA[blockIdx.x] = m0; g_pmaxA[blockIdx.x] = m1; }
    }
}

// ---------------- 2) finalize scales/zeros ----------------
__global__ void finalize_scales() {
    __shared__ float s0[256], s1[256], s2[256], s3[256];
    int t = threadIdx.x;
    float mnA = 3.4028235e38f, mxA = -3.4028235e38f;
    float mnB = 3.4028235e38f, mxB = -3.4028235e38f;
    for (int i = t; i < MMG; i += 256) {
        mnA = fminf(mnA, g_pminA[i]); mxA = fmaxf(mxA, g_pmaxA[i]);
        mnB = fminf(mnB, g_pminB[i]); mxB = fmaxf(mxB, g_pmaxB[i]);
    }
    s0[t] = mnA; s1[t] = mxA; s2[t] = mnB; s3[t] = mxB;
    __syncthreads();
    for (int o = 128; o > 0; o >>= 1) {
        if (t < o) {
            s0[t] = fminf(s0[t], s0[t + o]);
            s1[t] = fmaxf(s1[t], s1[t + o]);
            s2[t] = fminf(s2[t], s2[t + o]);
            s3[t] = fmaxf(s3[t], s3[t + o]);
        }
        __syncthreads();
    }
    if (t == 0) {
        float sA = __fdiv_rn(s1[0] - s0[0], 255.0f);
        float zA = rintf(__fdiv_rn(-s0[0], sA));
        float sB = __fdiv_rn(s3[0] - s2[0], 255.0f);
        float zB = rintf(__fdiv_rn(-s2[0], sB));
        g_scaleA = sA; g_zeroA = zA;
        g_scaleB = sB; g_zeroB = zB;
        g_sAB = sA * sB;
    }
}

// ---------------- 3a) quantize A (centered, bf16) ----------------
__global__ void quantize_A(const float* __restrict__ x, int n4) {
    int i = blockIdx.x * blockDim.x + threadIdx.x;
    if (i >= n4) return;
    float s = g_scaleA, z = g_zeroA;
    float4 v = ((const float4*)x)[i];
    float q0 = fminf(fmaxf(rintf(__fdiv_rn(v.x, s)) + z, 0.0f), 255.0f) - z;
    float q1 = fminf(fmaxf(rintf(__fdiv_rn(v.y, s)) + z, 0.0f), 255.0f) - z;
    float q2 = fminf(fmaxf(rintf(__fdiv_rn(v.z, s)) + z, 0.0f), 255.0f) - z;
    float q3 = fminf(fmaxf(rintf(__fdiv_rn(v.w, s)) + z, 0.0f), 255.0f) - z;
    __nv_bfloat162 p0 = make_bfloat162(__float2bfloat16_rn(q0), __float2bfloat16_rn(q1));
    __nv_bfloat162 p1 = make_bfloat162(__float2bfloat16_rn(q2), __float2bfloat16_rn(q3));
    uint32_t u0, u1;
    memcpy(&u0, &p0, 4); memcpy(&u1, &p1, 4);
    ((uint2*)g_qA)[i] = make_uint2(u0, u1);
}

// ---------------- 3b) quantize B fused with transpose: g_qB[n*K + k] ----------------
__global__ void quantize_B_T(const float* __restrict__ B) {
    __shared__ float tile[32][33];
    int n0 = blockIdx.x * 32, k0 = blockIdx.y * 32;
    int tx = threadIdx.x, ty = threadIdx.y;
    #pragma unroll
    for (int j = 0; j < 4; j++)
        tile[ty + 8 * j][tx] = B[(size_t)(k0 + ty + 8 * j) * N_DIM + n0 + tx];
    __syncthreads();
    float s = g_scaleB, z = g_zeroB;
    #pragma unroll
    for (int j = 0; j < 4; j++) {
        int nn = ty + 8 * j;   // local n
        int kk = tx;           // local k
        float v = tile[kk][nn];
        float q = fminf(fmaxf(rintf(__fdiv_rn(v, s)) + z, 0.0f), 255.0f) - z;
        g_qB[(size_t)(n0 + nn) * K_DIM + k0 + kk] = __float2bfloat16_rn(q);
    }
}

// ---------------- 4) GEMM: tcgen05 on sm_103a, mma.sync fallback on plain sm_103 ----------------
#define STAGES 4
#define BM 128
#define BN 256
#define BK 64
#define KT (K_DIM / BK)   // 32
// idesc: dtype=F32(bit4), atype=BF16(bit7), btype=BF16(bit10), N/8<<17, M/16<<24
#define GEMM_IDESC ((1u << 4) | (1u << 7) | (1u << 10) | ((BN / 8) << 17) | ((BM / 16) << 24))

// dynamic SMEM layout (tcgen05 path)
#define SM_TPTR_OFF   0
#define SM_FULL_OFF   16
#define SM_EMPTY_OFF  48
#define SM_DONE_OFF   80
#define SM_A_OFF(s)   (1024 + (s) * 16384)        // 128 rows x 128B per stage
#define SM_B_OFF(s)   (66560 + (s) * 32768)       // 256 rows x 128B per stage
#define SMEM_TOTAL    197632

__global__ void __launch_bounds__(256, 1) __cluster_dims__(1, 1, 1)
gemm_tc(float* __restrict__ C) {
    extern __shared__ char smem[];
    const int tid = threadIdx.x, wid = tid >> 5, lane = tid & 31;
    const int bm = blockIdx.y * BM;
    const int bn = blockIdx.x * BN;

#if HAS_TCGEN05
    // ================= tcgen05 path (sm_103a) =================
    const uint32_t sb = smem_u32(smem);

    if (tid == 0) {
        #pragma unroll
        for (int s = 0; s < STAGES; s++) {
            MBARRIER_INIT(sb + SM_FULL_OFF + 8 * s, 128);
            MBARRIER_INIT(sb + SM_EMPTY_OFF + 8 * s, 1);
        }
        MBARRIER_INIT(sb + SM_DONE_OFF, 1);
    }
    if (wid == 4) {
        TCGEN05_ALLOC(sb + SM_TPTR_OFF, 256);
    } else {
        TCGEN05_RELINQUISH();
    }
    __syncthreads();

    uint32_t tmem;
    asm volatile("ld.shared.b32 %0, [%1];" : "=r"(tmem) : "r"(sb + SM_TPTR_OFF));

    if (wid == 4) {
        // ---- MMA warp ----
        TCGEN05_FENCE_AFTER();
        int ph = 0;
        for (int kt = 0; kt < KT; kt++) {
            const int s = kt & 3;
            MBARRIER_WAIT_PARITY(sb + SM_FULL_OFF + 8 * s, ph);
            if (s == 3) ph ^= 1;
            if (elect_one_pred()) {
                const uint64_t ad = MAKE_SMEM_DESC(sb + SM_A_OFF(s));
                const uint64_t bd = MAKE_SMEM_DESC(sb + SM_B_OFF(s));
                #pragma unroll
                for (int ks = 0; ks < 4; ks++) {
                    uint32_t en = (kt > 0 || ks > 0) ? 1u : 0u;
                    mma_f16_ss(tmem, ad + ks * 2, bd + ks * 2, GEMM_IDESC, en);
                }
                TCGEN05_COMMIT(sb + SM_EMPTY_OFF + 8 * s);
            }
        }
        if (elect_one_pred()) TCGEN05_COMMIT(sb + SM_DONE_OFF);
    } else if (wid < 4) {
        // ---- producer warps 0-3 (128 threads) ----
        const __nv_bfloat16* __restrict__ Aq = g_qA;
        const __nv_bfloat16* __restrict__ Bq = g_qB;
        int eph = 1;
        for (int kt = 0; kt < KT; kt++) {
            const int s = kt & 3;
            MBARRIER_WAIT_PARITY(sb + SM_EMPTY_OFF + 8 * s, eph);
            if (s == 3) eph ^= 1;
            const int k0 = kt * BK;
            const uint32_t abase = sb + SM_A_OFF(s);
            #pragma unroll
            for (int i = 0; i < 8; i++) {
                int c = tid + i * 128;          // 0..1023
                int row = c >> 3, col = c & 7;  // 128 rows x 8 chunks
                uint32_t boff = (uint32_t)(row * 128 + col * 16);
                cp_async16(abase + SMEM_SWIZZLE_128B(boff),
                           Aq + (size_t)(bm + row) * K_DIM + k0 + col * 8);
            }
            const uint32_t bbase = sb + SM_B_OFF(s);
            #pragma unroll
            for (int i = 0; i < 16; i++) {
                int c = tid + i * 128;          // 0..2047
                int row = c >> 3, col = c & 7;  // 256 rows x 8 chunks
                uint32_t boff = (uint32_t)(row * 128 + col * 16);
                cp_async16(bbase + SMEM_SWIZZLE_128B(boff),
                           Bq + (size_t)(bn + row) * K_DIM + k0 + col * 8);
            }
            cp_commit();
            if (kt >= 2) {
                cp_wait<2>();
                FENCE_PROXY_ASYNC();
                MBARRIER_ARRIVE(sb + SM_FULL_OFF + 8 * ((kt - 2) & 3));
            }
        }
        cp_wait<1>();
        FENCE_PROXY_ASYNC();
        MBARRIER_ARRIVE(sb + SM_FULL_OFF + 8 * ((KT - 2) & 3));
        cp_wait<0>();
        FENCE_PROXY_ASYNC();
        MBARRIER_ARRIVE(sb + SM_FULL_OFF + 8 * ((KT - 1) & 3));
    }
    // warps 5-7: nothing until completion wait

    // ---- everyone waits for MMA chain completion ----
    MBARRIER_WAIT_PARITY(sb + SM_DONE_OFF, 0);
    TCGEN05_FENCE_AFTER();

    if (wid < 4) {
        const float sc = g_sAB;
        const int row = bm + wid * 32 + lane;
        float* __restrict__ crow = C + (size_t)row * N_DIM + bn;
        #pragma unroll
        for (int ch = 0; ch < 8; ch++) {
            uint32_t r[32];
            TCGEN05_LD_32X32B_X32(r, tmem + ch * 32);
            TCGEN05_WAIT_LD();
            #pragma unroll
            for (int j = 0; j < 8; j++) {
                float4 v;
                v.x = __uint_as_float(r[4 * j + 0]) * sc;
                v.y = __uint_as_float(r[4 * j + 1]) * sc;
                v.z = __uint_as_float(r[4 * j + 2]) * sc;
                v.w = __uint_as_float(r[4 * j + 3]) * sc;
                *(float4*)(crow + ch * 32 + 4 * j) = v;
            }
        }
        TCGEN05_FENCE_BEFORE();
    }
    __syncthreads();
    if (tid == 0) {
        #pragma unroll
        for (int s = 0; s < STAGES; s++) {
            MBARRIER_INVAL(sb + SM_FULL_OFF + 8 * s);
            MBARRIER_INVAL(sb + SM_EMPTY_OFF + 8 * s);
        }
        MBARRIER_INVAL(sb + SM_DONE_OFF);
    }
    __syncthreads();
    if (wid == 4) {
        TCGEN05_DEALLOC(tmem, 256);
    }

#else
    // ================= fallback path (plain sm_103): mma.sync m16n8k16 =================
    // Processes the 128x256 block tile as two 128x128 halves.
    #define LDA_S 40
    __nv_bfloat16* As = (__nv_bfloat16*)smem;                 // 2*128*40*2 = 20480 B
    __nv_bfloat16* Bs = As + 2 * 128 * LDA_S;                 // 2*128*40*2 = 20480 B

    const int warpM = wid & 3;   // 4 warps along M (32 rows each)
    const int warpN = wid >> 2;  // 2 warps along N (64 cols each)
    const __nv_bfloat16* __restrict__ Aq = g_qA;
    const __nv_bfloat16* __restrict__ Bq = g_qB;

    for (int half = 0; half < 2; half++) {
        const int bnh = bn + half * 128;

        float acc[2][8][4];
        #pragma unroll
        for (int mt = 0; mt < 2; mt++)
            #pragma unroll
            for (int nt = 0; nt < 8; nt++)
                #pragma unroll
                for (int r = 0; r < 4; r++)
                    acc[mt][nt][r] = 0.0f;

        auto load_stage = [&](int kt, int buf) {
            const int k0 = kt * 32;
            #pragma unroll
            for (int c = tid; c < 512; c += 256) {
                int row = c >> 2, cc = c & 3;
                cp_async16(smem_u32(&As[(buf * 128 + row) * LDA_S + cc * 8]),
                           Aq + (size_t)(bm + row) * K_DIM + k0 + cc * 8);
            }
            #pragma unroll
            for (int c = tid; c < 512; c += 256) {
                int row = c >> 2, cc = c & 3;
                cp_async16(smem_u32(&Bs[(buf * 128 + row) * LDA_S + cc * 8]),
                           Bq + (size_t)(bnh + row) * K_DIM + k0 + cc * 8);
            }
            cp_commit();
        };

        const int KT32 = K_DIM / 32;  // 64
        __syncthreads();
        load_stage(0, 0);

        for (int kt = 0; kt < KT32; kt++) {
            const int buf = kt & 1;
            if (kt + 1 < KT32) {
                load_stage(kt + 1, (kt + 1) & 1);
                cp_wait<1>();
            } else {
                cp_wait<0>();
            }
            __syncthreads();

            #pragma unroll
            for (int ks = 0; ks < 2; ks++) {
                uint32_t a[2][4];
                #pragma unroll
                for (int mt = 0; mt < 2; mt++) {
                    const __nv_bfloat16* p =
                        &As[(buf * 128 + warpM * 32 + mt * 16 + (lane & 15)) * LDA_S + ks * 16 + (lane >> 4) * 8];
                    ldsm_x4(a[mt], smem_u32(p));
                }
                uint32_t b[8][2];
                #pragma unroll
                for (int np = 0; np < 4; np++) {
                    const __nv_bfloat16* p =
                        &Bs[(buf * 128 + warpN * 64 + np * 16 + (lane & 15)) * LDA_S + ks * 16 + (lane >> 4) * 8];
                    uint32_t r[4];
                    ldsm_x4(r, smem_u32(p));
                    b[2 * np][0] = r[0];     b[2 * np][1] = r[2];
                    b[2 * np + 1][0] = r[1]; b[2 * np + 1][1] = r[3];
                }
                #pragma unroll
                for (int mt = 0; mt < 2; mt++)
                    #pragma unroll
                    for (int nt = 0; nt < 8; nt++)
                        mma_bf16(acc[mt][nt], a[mt], b[nt]);
            }
            __syncthreads();
        }

        const float s = g_sAB;
        const int groupID = lane >> 2, tig = lane & 3;
        #pragma unroll
        for (int mt = 0; mt < 2; mt++) {
            #pragma unroll
            for (int nt = 0; nt < 8; nt++) {
                int row0 = bm + warpM * 32 + mt * 16 + groupID;
                int col  = bnh + warpN * 64 + nt * 8 + tig * 2;
                float2 v0 = make_float2(acc[mt][nt][0] * s, acc[mt][nt][1] * s);
                float2 v1 = make_float2(acc[mt][nt][2] * s, acc[mt][nt][3] * s);
                *(float2*)&C[(size_t)row0 * N_DIM + col]       = v0;
                *(float2*)&C[(size_t)(row0 + 8) * N_DIM + col] = v1;
            }
        }
    }
    #undef LDA_S
#endif
}

// ---------------- launch ----------------
extern "C" void kernel_launch(void* const* d_in, const int* in_sizes, int n_in,
                              void* d_out, int out_size) {
    const float* A = (const float*)d_in[0];  // [4096, 2048]
    const float* B = (const float*)d_in[1];  // [2048, 4096]
    float* C = (float*)d_out;                // [4096, 4096]

    const int nA = M_DIM * K_DIM;
    const int nB = K_DIM * N_DIM;

    minmax_partial<<<MMG, 256>>>(A, nA, 0);
    minmax_partial<<<MMG, 256>>>(B, nB, 1);
    finalize_scales<<<1, 256>>>();

    quantize_A<<<(nA / 4 + 255) / 256, 256>>>(A, nA / 4);
    dim3 tgrid(N_DIM / 32, K_DIM / 32);
    quantize_B_T<<<tgrid, dim3(32, 8)>>>(B);

    static int smem_set = 0;
    if (!smem_set) {
        cudaFuncSetAttribute(gemm_tc, cudaFuncAttributeMaxDynamicSharedMemorySize, SMEM_TOTAL);
        smem_set = 1;
    }
    dim3 grid(N_DIM / BN, M_DIM / BM);  // 16 x 32
    gemm_tc<<<grid, 256, SMEM_TOTAL>>>(C);
}